// round 1
// baseline (speedup 1.0000x reference)
#include <cuda_runtime.h>
#include <math.h>

#define D_MODEL 2048
#define NH 16
#define DH 128
#define BB 2
#define SS 2048
#define MTOT (BB*SS)      /* 4096 rows of x */
#define NPROJ (NH*DH)     /* 2048 */

// ---------------- scratch (static __device__, no allocations) ----------------
__device__ float g_q[(size_t)BB*NH*SS*DH];    // [b,h,s,d]
__device__ float g_k[(size_t)BB*NH*SS*DH];
__device__ float g_v[(size_t)BB*NH*SS*DH];
__device__ float g_ctx[(size_t)MTOT*NPROJ];   // [b,s, h*DH+d]

// ---------------- GEMM: C = A[M,K] @ B[K,N] + bias ----------------
// MODE 0: scatter into [b,h,s,d] (for Q/K/V).  MODE 1: row-major [M,N].
template<int MODE>
__global__ void __launch_bounds__(256) gemm128(const float* __restrict__ A,
                                               const float* __restrict__ B,
                                               const float* __restrict__ bias,
                                               float* __restrict__ C,
                                               int M, int N, int K)
{
    __shared__ float As[16][132];   // transposed A tile: As[k][m]
    __shared__ float Bs[16][132];   // Bs[k][n]
    const int t  = threadIdx.x;
    const int bm = blockIdx.y * 128;
    const int bn = blockIdx.x * 128;
    const int tx = t & 15;          // col group
    const int ty = t >> 4;          // row group

    float acc[8][8];
#pragma unroll
    for (int r = 0; r < 8; r++)
#pragma unroll
        for (int c = 0; c < 8; c++) acc[r][c] = 0.f;

    const float* Ab = A + (size_t)bm * K;
    const float* Bb = B + bn;

    for (int k0 = 0; k0 < K; k0 += 16) {
#pragma unroll
        for (int i = 0; i < 2; i++) {
            int idx = t + i * 256;
            // A tile: 128 rows x 16 k  -> 512 float4
            int ar = idx >> 2, ac4 = idx & 3;
            float4 va = *(const float4*)(Ab + (size_t)ar * K + k0 + ac4 * 4);
            As[ac4*4+0][ar] = va.x; As[ac4*4+1][ar] = va.y;
            As[ac4*4+2][ar] = va.z; As[ac4*4+3][ar] = va.w;
            // B tile: 16 k x 128 n -> 512 float4
            int br = idx >> 5, bc4 = idx & 31;
            float4 vb = *(const float4*)(Bb + (size_t)(k0 + br) * N + bc4 * 4);
            *(float4*)(&Bs[br][bc4*4]) = vb;
        }
        __syncthreads();
#pragma unroll
        for (int k = 0; k < 16; k++) {
            float a[8], b[8];
            *(float4*)(a)   = *(const float4*)(&As[k][ty*8]);
            *(float4*)(a+4) = *(const float4*)(&As[k][ty*8+4]);
            *(float4*)(b)   = *(const float4*)(&Bs[k][tx*8]);
            *(float4*)(b+4) = *(const float4*)(&Bs[k][tx*8+4]);
#pragma unroll
            for (int r = 0; r < 8; r++)
#pragma unroll
                for (int c = 0; c < 8; c++)
                    acc[r][c] += a[r] * b[c];
        }
        __syncthreads();
    }

#pragma unroll
    for (int r = 0; r < 8; r++) {
        int m = bm + ty*8 + r;
#pragma unroll
        for (int c = 0; c < 8; c++) {
            int n = bn + tx*8 + c;
            float val = acc[r][c] + bias[n];
            if (MODE == 0) {
                int b  = m >> 11;        // m / SS
                int s  = m & (SS - 1);
                int h  = n >> 7;         // n / DH
                int d  = n & (DH - 1);
                C[(((size_t)(b*NH + h)) * SS + s) * DH + d] = val;
            } else {
                C[(size_t)m * N + n] = val;
            }
        }
    }
}

// ---------------- Flash attention (causal) ----------------
// grid: (SS/64, BB*NH), 256 threads. Br=Bc=64, d=128.
#define FA_SMEM_FLOATS (64*128*3 + 64*68 + 64*4 + 64*4)
__global__ void __launch_bounds__(256) flash_kernel(const float* __restrict__ Q,
                                                    const float* __restrict__ K,
                                                    const float* __restrict__ V,
                                                    float* __restrict__ ctx)
{
    extern __shared__ float sm[];
    float* sQ  = sm;                // [64][128] row-major
    float* sK  = sQ + 64*128;       // [64][128] XOR-swizzled 16B chunks
    float* sV  = sK + 64*128;       // [64][128] row-major
    float* sS  = sV + 64*128;       // [64][68]
    float* s_m  = sS + 64*68;       // running max
    float* s_l  = s_m + 64;         // running sum
    float* s_mn = s_l + 64;         // new max
    float* s_sc = s_mn + 64;        // rescale factor
    float* s_ps = s_sc + 64;        // partial sums [64][4]

    const int t  = threadIdx.x;
    const int qi = blockIdx.x;
    const int bh = blockIdx.y;
    const size_t headbase = (size_t)bh * SS * DH;

    const float4* Qg = (const float4*)(Q + headbase + (size_t)qi * 64 * DH);
#pragma unroll
    for (int i = 0; i < 8; i++) {
        int e = i*256 + t;
        int r = e >> 5, c4 = e & 31;
        *(float4*)(sQ + r*128 + c4*4) = Qg[e];
    }
    if (t < 64) { s_m[t] = -1e30f; s_l[t] = 0.f; }

    float o[4][8];
#pragma unroll
    for (int r = 0; r < 4; r++)
#pragma unroll
        for (int c = 0; c < 8; c++) o[r][c] = 0.f;

    const int ti  = t >> 4;        // 0..15
    const int tj  = t & 15;        // 0..15
    const int i0  = ti * 4;        // rows (score + PV)
    const int j0s = tj * 4;        // score cols
    const int j0v = tj * 8;        // PV cols
    const int row = t >> 2;        // softmax row
    const int seg = t & 3;         // softmax col segment
    const float scale = 0.08838834764831845f;  // 1/sqrt(128)

    for (int kj = 0; kj <= qi; kj++) {
        __syncthreads();           // previous PV done before tile overwrite
        const float4* Kg = (const float4*)(K + headbase + (size_t)kj * 64 * DH);
        const float4* Vg = (const float4*)(V + headbase + (size_t)kj * 64 * DH);
#pragma unroll
        for (int i = 0; i < 8; i++) {
            int e = i*256 + t;
            int r = e >> 5, c4 = e & 31;
            int sw = c4 ^ ((r >> 2) & 7);
            *(float4*)(sK + r*128 + sw*4) = Kg[e];
            *(float4*)(sV + r*128 + c4*4) = Vg[e];
        }
        __syncthreads();

        // ---- scores: 4x4 per thread ----
        float acc[4][4];
#pragma unroll
        for (int r = 0; r < 4; r++)
#pragma unroll
            for (int c = 0; c < 4; c++) acc[r][c] = 0.f;

#pragma unroll 8
        for (int k = 0; k < 128; k += 4) {
            float4 qa[4], kb[4];
#pragma unroll
            for (int r = 0; r < 4; r++)
                qa[r] = *(const float4*)(sQ + (i0+r)*128 + k);
            int chunk = (k >> 2) ^ (tj & 7);
#pragma unroll
            for (int c = 0; c < 4; c++)
                kb[c] = *(const float4*)(sK + (j0s+c)*128 + chunk*4);
#pragma unroll
            for (int r = 0; r < 4; r++)
#pragma unroll
                for (int c = 0; c < 4; c++) {
                    acc[r][c] += qa[r].x * kb[c].x;
                    acc[r][c] += qa[r].y * kb[c].y;
                    acc[r][c] += qa[r].z * kb[c].z;
                    acc[r][c] += qa[r].w * kb[c].w;
                }
        }
#pragma unroll
        for (int r = 0; r < 4; r++)
#pragma unroll
            for (int c = 0; c < 4; c++) {
                float v = acc[r][c] * scale;
                if (kj == qi && (j0s + c) > (i0 + r)) v = -1e30f;
                sS[(i0+r)*68 + j0s + c] = v;
            }
        __syncthreads();

        // ---- online softmax (4 threads per row; redundant stats) ----
        float mold = s_m[row];
        float rmax = -1e30f;
#pragma unroll 16
        for (int j = 0; j < 64; j++) rmax = fmaxf(rmax, sS[row*68 + j]);
        float mnew = fmaxf(mold, rmax);
        float part = 0.f;
#pragma unroll
        for (int j = seg*16; j < seg*16 + 16; j++) {
            float p = __expf(sS[row*68 + j] - mnew);
            sS[row*68 + j] = p;
            part += p;
        }
        s_ps[row*4 + seg] = part;
        if (seg == 0) { s_mn[row] = mnew; s_sc[row] = __expf(mold - mnew); }
        __syncthreads();
        if (t < 64) {
            s_l[t] = s_l[t] * s_sc[t]
                   + s_ps[t*4] + s_ps[t*4+1] + s_ps[t*4+2] + s_ps[t*4+3];
            s_m[t] = s_mn[t];
        }

        // ---- PV: 4 rows x 8 cols per thread ----
#pragma unroll
        for (int r = 0; r < 4; r++) {
            float sc = s_sc[i0 + r];
#pragma unroll
            for (int c = 0; c < 8; c++) o[r][c] *= sc;
        }
#pragma unroll 4
        for (int kk = 0; kk < 64; kk += 4) {
            float4 p[4];
#pragma unroll
            for (int r = 0; r < 4; r++)
                p[r] = *(const float4*)(sS + (i0+r)*68 + kk);
#pragma unroll
            for (int u = 0; u < 4; u++) {
                float4 va = *(const float4*)(sV + (kk+u)*128 + j0v);
                float4 vb = *(const float4*)(sV + (kk+u)*128 + j0v + 4);
#pragma unroll
                for (int r = 0; r < 4; r++) {
                    float pr = (u == 0) ? p[r].x : (u == 1) ? p[r].y
                             : (u == 2) ? p[r].z : p[r].w;
                    o[r][0] += pr * va.x; o[r][1] += pr * va.y;
                    o[r][2] += pr * va.z; o[r][3] += pr * va.w;
                    o[r][4] += pr * vb.x; o[r][5] += pr * vb.y;
                    o[r][6] += pr * vb.z; o[r][7] += pr * vb.w;
                }
            }
        }
    }

    __syncthreads();   // s_l final
    const int b = bh / NH, h = bh % NH;
#pragma unroll
    for (int r = 0; r < 4; r++) {
        float inv = 1.f / s_l[i0 + r];
        int srow = qi*64 + i0 + r;
        float* dst = ctx + ((size_t)(b*SS + srow)) * NPROJ + h*DH + j0v;
        float4 w0, w1;
        w0.x = o[r][0]*inv; w0.y = o[r][1]*inv; w0.z = o[r][2]*inv; w0.w = o[r][3]*inv;
        w1.x = o[r][4]*inv; w1.y = o[r][5]*inv; w1.z = o[r][6]*inv; w1.w = o[r][7]*inv;
        *(float4*)(dst)     = w0;
        *(float4*)(dst + 4) = w1;
    }
}

// ---------------- launch ----------------
extern "C" void kernel_launch(void* const* d_in, const int* in_sizes, int n_in,
                              void* d_out, int out_size)
{
    const float* x  = (const float*)d_in[0];
    const float* Wq = (const float*)d_in[1];
    const float* bq = (const float*)d_in[2];
    const float* Wk = (const float*)d_in[3];
    const float* bk = (const float*)d_in[4];
    const float* Wv = (const float*)d_in[5];
    const float* bv = (const float*)d_in[6];
    const float* Wo = (const float*)d_in[7];
    const float* bo = (const float*)d_in[8];
    float* out = (float*)d_out;

    float *qp, *kp, *vp, *cp;
    cudaGetSymbolAddress((void**)&qp, g_q);
    cudaGetSymbolAddress((void**)&kp, g_k);
    cudaGetSymbolAddress((void**)&vp, g_v);
    cudaGetSymbolAddress((void**)&cp, g_ctx);

    const int smem_bytes = FA_SMEM_FLOATS * sizeof(float);
    cudaFuncSetAttribute(flash_kernel,
                         cudaFuncAttributeMaxDynamicSharedMemorySize, smem_bytes);

    dim3 ggrid(NPROJ/128, MTOT/128);   // (16, 32)
    gemm128<0><<<ggrid, 256>>>(x, Wq, bq, qp, MTOT, NPROJ, D_MODEL);
    gemm128<0><<<ggrid, 256>>>(x, Wk, bk, kp, MTOT, NPROJ, D_MODEL);
    gemm128<0><<<ggrid, 256>>>(x, Wv, bv, vp, MTOT, NPROJ, D_MODEL);

    dim3 fgrid(SS/64, BB*NH);          // (32, 32)
    flash_kernel<<<fgrid, 256, smem_bytes>>>(qp, kp, vp, cp);

    gemm128<1><<<ggrid, 256>>>(cp, Wo, bo, out, MTOT, D_MODEL, D_MODEL);
}

// round 3
// speedup vs baseline: 1.8367x; 1.8367x over previous
#include <cuda_runtime.h>
#include <cuda_bf16.h>
#include <cstdint>
#include <math.h>

#define D_MODEL 2048
#define NH 16
#define DH 128
#define BB 2
#define SS 2048
#define MTOT (BB*SS)      /* 4096 */
#define NPROJ (NH*DH)     /* 2048 */

// ---------------- scratch ----------------
__device__ float g_q[(size_t)BB*NH*SS*DH];
__device__ float g_k[(size_t)BB*NH*SS*DH];
__device__ float g_v[(size_t)BB*NH*SS*DH];
__device__ float g_ctx[(size_t)MTOT*NPROJ];
__device__ __nv_bfloat16 g_xh[(size_t)MTOT*D_MODEL];
__device__ __nv_bfloat16 g_xl[(size_t)MTOT*D_MODEL];
__device__ __nv_bfloat16 g_ch[(size_t)MTOT*NPROJ];
__device__ __nv_bfloat16 g_cl[(size_t)MTOT*NPROJ];
__device__ __nv_bfloat16 g_wqh[(size_t)D_MODEL*NPROJ];
__device__ __nv_bfloat16 g_wql[(size_t)D_MODEL*NPROJ];
__device__ __nv_bfloat16 g_wkh[(size_t)D_MODEL*NPROJ];
__device__ __nv_bfloat16 g_wkl[(size_t)D_MODEL*NPROJ];
__device__ __nv_bfloat16 g_wvh[(size_t)D_MODEL*NPROJ];
__device__ __nv_bfloat16 g_wvl[(size_t)D_MODEL*NPROJ];
__device__ __nv_bfloat16 g_woh[(size_t)D_MODEL*NPROJ];
__device__ __nv_bfloat16 g_wol[(size_t)D_MODEL*NPROJ];

// ---------------- helpers ----------------
__device__ __forceinline__ uint32_t smem_u32(const void* p) {
    uint32_t a;
    asm("{ .reg .u64 t; cvta.to.shared.u64 t, %1; cvt.u32.u64 %0, t; }" : "=r"(a) : "l"(p));
    return a;
}
#define CP_ASYNC16(dst, src) \
    asm volatile("cp.async.cg.shared.global [%0], [%1], 16;" :: "r"(dst), "l"(src))
#define CP_COMMIT() asm volatile("cp.async.commit_group;" ::: "memory")
#define CP_WAIT1() asm volatile("cp.async.wait_group 1;" ::: "memory")
#define CP_WAIT0() asm volatile("cp.async.wait_group 0;" ::: "memory")

__device__ __forceinline__ void mma_bf16(float* c, uint32_t a0, uint32_t a1,
                                         uint32_t a2, uint32_t a3,
                                         uint32_t b0, uint32_t b1) {
    asm volatile(
        "mma.sync.aligned.m16n8k16.row.col.f32.bf16.bf16.f32 "
        "{%0,%1,%2,%3}, {%4,%5,%6,%7}, {%8,%9}, {%0,%1,%2,%3};"
        : "+f"(c[0]), "+f"(c[1]), "+f"(c[2]), "+f"(c[3])
        : "r"(a0), "r"(a1), "r"(a2), "r"(a3), "r"(b0), "r"(b1));
}

// ---------------- conversion kernels ----------------
__global__ void __launch_bounds__(256) cvt_hilo(const float* __restrict__ src,
                                                __nv_bfloat16* __restrict__ hi,
                                                __nv_bfloat16* __restrict__ lo, int n4)
{
    int i = blockIdx.x * 256 + threadIdx.x;
    if (i >= n4) return;
    float4 v = ((const float4*)src)[i];
    __nv_bfloat16 h0 = __float2bfloat16(v.x), h1 = __float2bfloat16(v.y);
    __nv_bfloat16 h2 = __float2bfloat16(v.z), h3 = __float2bfloat16(v.w);
    __nv_bfloat16 l0 = __float2bfloat16(v.x - __bfloat162float(h0));
    __nv_bfloat16 l1 = __float2bfloat16(v.y - __bfloat162float(h1));
    __nv_bfloat16 l2 = __float2bfloat16(v.z - __bfloat162float(h2));
    __nv_bfloat16 l3 = __float2bfloat16(v.w - __bfloat162float(h3));
    __nv_bfloat162 ph0; ph0.x = h0; ph0.y = h1;
    __nv_bfloat162 ph1; ph1.x = h2; ph1.y = h3;
    __nv_bfloat162 pl0; pl0.x = l0; pl0.y = l1;
    __nv_bfloat162 pl1; pl1.x = l2; pl1.y = l3;
    ((__nv_bfloat162*)hi)[i*2]   = ph0;
    ((__nv_bfloat162*)hi)[i*2+1] = ph1;
    ((__nv_bfloat162*)lo)[i*2]   = pl0;
    ((__nv_bfloat162*)lo)[i*2+1] = pl1;
}

// W[K][N] -> Wt hi/lo [N][K]
__global__ void __launch_bounds__(256) transcvt(const float* __restrict__ W,
                                                __nv_bfloat16* __restrict__ th,
                                                __nv_bfloat16* __restrict__ tl)
{
    __shared__ float tile[32][33];
    int nb = blockIdx.x * 32, kb = blockIdx.y * 32;
    int tx = threadIdx.x & 31, ty = threadIdx.x >> 5;
#pragma unroll
    for (int j = 0; j < 4; j++)
        tile[ty + j*8][tx] = W[(size_t)(kb + ty + j*8) * D_MODEL + nb + tx];
    __syncthreads();
#pragma unroll
    for (int j = 0; j < 4; j++) {
        int n = nb + ty + j*8;
        float v = tile[tx][ty + j*8];
        __nv_bfloat16 h = __float2bfloat16(v);
        __nv_bfloat16 l = __float2bfloat16(v - __bfloat162float(h));
        th[(size_t)n * D_MODEL + kb + tx] = h;
        tl[(size_t)n * D_MODEL + kb + tx] = l;
    }
}

// ---------------- tensor-core GEMM via mma.sync ----------------
// A hi/lo [M][K] bf16 row-major; B hi/lo [N][K] bf16 (K-major).
// Block 128x128, Kt=32, double-buffered cp.async. 8 warps = 2(M) x 4(N).
#define OFF_AH 0
#define OFF_AL 8192
#define OFF_BH 16384
#define OFF_BL 24576
#define BUF_STRIDE 32768
#define GEMM_SMEM (2*BUF_STRIDE)

// swizzled byte offset within a tile: row (0..127), 16B chunk (0..3)
__device__ __forceinline__ int swzoff(int row, int ch) {
    return row * 64 + (((ch ^ (row >> 1)) & 3) * 16);
}

template<int MODE>
__global__ void __launch_bounds__(256) gemm_mma(const __nv_bfloat16* __restrict__ Ah,
                                                const __nv_bfloat16* __restrict__ Al,
                                                const __nv_bfloat16* __restrict__ Bh,
                                                const __nv_bfloat16* __restrict__ Bl,
                                                const float* __restrict__ bias,
                                                float* __restrict__ C,
                                                int M, int N, int K)
{
    extern __shared__ char smb[];
    const uint32_t sb = smem_u32(smb);
    const int t = threadIdx.x;
    const int lane = t & 31;
    const int wid = t >> 5;
    const int g = lane >> 2;          // group id (row within frag)
    const int tid4 = lane & 3;        // thread-in-group
    const int warp_m = wid >> 2;      // 0..1
    const int warp_n = wid & 3;       // 0..3
    const int bm = blockIdx.y * 128, bn = blockIdx.x * 128;

    // per-thread gmem load coords: rows t>>2 and t>>2+64, chunk t&3
    const int lr = t >> 2;
    const int lc = t & 3;
    const int iters = K >> 5;         // Kt = 32

    float acc[4][4][4];
#pragma unroll
    for (int a = 0; a < 4; a++)
#pragma unroll
        for (int b = 0; b < 4; b++)
#pragma unroll
            for (int c = 0; c < 4; c++) acc[a][b][c] = 0.f;

    // ---- async load of one k-tile into buffer ----
    auto issue = [&](int it, int buf) {
        const size_t koff = (size_t)it * 32 + lc * 8;
        const uint32_t bufb = sb + buf * BUF_STRIDE;
#pragma unroll
        for (int i = 0; i < 2; i++) {
            int r = lr + i * 64;
            uint32_t d = bufb + swzoff(r, lc);
            const __nv_bfloat16* sa = Ah + (size_t)(bm + r) * K + koff;
            const __nv_bfloat16* sal = Al + (size_t)(bm + r) * K + koff;
            const __nv_bfloat16* sbh = Bh + (size_t)(bn + r) * K + koff;
            const __nv_bfloat16* sbl = Bl + (size_t)(bn + r) * K + koff;
            CP_ASYNC16(d + OFF_AH, sa);
            CP_ASYNC16(d + OFF_AL, sal);
            CP_ASYNC16(d + OFF_BH, sbh);
            CP_ASYNC16(d + OFF_BL, sbl);
        }
    };

    issue(0, 0);
    CP_COMMIT();

    for (int it = 0; it < iters; it++) {
        const int buf = it & 1;
        if (it + 1 < iters) { issue(it + 1, buf ^ 1); CP_COMMIT(); CP_WAIT1(); }
        else                { CP_WAIT0(); }
        __syncthreads();

        const char* cb = smb + buf * BUF_STRIDE;
#pragma unroll
        for (int ks = 0; ks < 2; ks++) {
            const int ch0 = ks * 2;
            uint32_t afr[4][4], bhf[4][2], blf[4][2];
            // A-hi fragments
#pragma unroll
            for (int mf = 0; mf < 4; mf++) {
                int r0 = warp_m * 64 + mf * 16 + g;
                afr[mf][0] = *(const uint32_t*)(cb + OFF_AH + swzoff(r0, ch0) + tid4*4);
                afr[mf][1] = *(const uint32_t*)(cb + OFF_AH + swzoff(r0+8, ch0) + tid4*4);
                afr[mf][2] = *(const uint32_t*)(cb + OFF_AH + swzoff(r0, ch0+1) + tid4*4);
                afr[mf][3] = *(const uint32_t*)(cb + OFF_AH + swzoff(r0+8, ch0+1) + tid4*4);
            }
            // B-hi and B-lo fragments
#pragma unroll
            for (int nf = 0; nf < 4; nf++) {
                int rb = warp_n * 32 + nf * 8 + g;
                bhf[nf][0] = *(const uint32_t*)(cb + OFF_BH + swzoff(rb, ch0) + tid4*4);
                bhf[nf][1] = *(const uint32_t*)(cb + OFF_BH + swzoff(rb, ch0+1) + tid4*4);
                blf[nf][0] = *(const uint32_t*)(cb + OFF_BL + swzoff(rb, ch0) + tid4*4);
                blf[nf][1] = *(const uint32_t*)(cb + OFF_BL + swzoff(rb, ch0+1) + tid4*4);
            }
            // Ah*Bh and Ah*Bl
#pragma unroll
            for (int mf = 0; mf < 4; mf++)
#pragma unroll
                for (int nf = 0; nf < 4; nf++) {
                    mma_bf16(acc[mf][nf], afr[mf][0], afr[mf][1], afr[mf][2], afr[mf][3],
                             bhf[nf][0], bhf[nf][1]);
                    mma_bf16(acc[mf][nf], afr[mf][0], afr[mf][1], afr[mf][2], afr[mf][3],
                             blf[nf][0], blf[nf][1]);
                }
            // A-lo fragments, Al*Bh
#pragma unroll
            for (int mf = 0; mf < 4; mf++) {
                int r0 = warp_m * 64 + mf * 16 + g;
                afr[mf][0] = *(const uint32_t*)(cb + OFF_AL + swzoff(r0, ch0) + tid4*4);
                afr[mf][1] = *(const uint32_t*)(cb + OFF_AL + swzoff(r0+8, ch0) + tid4*4);
                afr[mf][2] = *(const uint32_t*)(cb + OFF_AL + swzoff(r0, ch0+1) + tid4*4);
                afr[mf][3] = *(const uint32_t*)(cb + OFF_AL + swzoff(r0+8, ch0+1) + tid4*4);
            }
#pragma unroll
            for (int mf = 0; mf < 4; mf++)
#pragma unroll
                for (int nf = 0; nf < 4; nf++)
                    mma_bf16(acc[mf][nf], afr[mf][0], afr[mf][1], afr[mf][2], afr[mf][3],
                             bhf[nf][0], bhf[nf][1]);
        }
        __syncthreads();
    }

    // ---- epilogue ----
#pragma unroll
    for (int nf = 0; nf < 4; nf++) {
        const int n = bn + warp_n * 32 + nf * 8 + tid4 * 2;
        const float2 bv = *(const float2*)(bias + n);
#pragma unroll
        for (int mf = 0; mf < 4; mf++) {
#pragma unroll
            for (int half = 0; half < 2; half++) {
                const int m = bm + warp_m * 64 + mf * 16 + g + half * 8;
                float2 w;
                w.x = acc[mf][nf][half*2 + 0] + bv.x;
                w.y = acc[mf][nf][half*2 + 1] + bv.y;
                size_t idx;
                if (MODE == 0) {
                    int b = m >> 11, s = m & (SS - 1), h = bn >> 7, d = n & (DH - 1);
                    idx = (((size_t)(b * NH + h)) * SS + s) * DH + d;
                } else {
                    idx = (size_t)m * N + n;
                }
                *(float2*)(C + idx) = w;
            }
        }
    }
}

// ---------------- Flash attention (causal, fp32, unchanged) ----------------
#define FA_SMEM_FLOATS (64*128*3 + 64*68 + 64*4 + 64*4)
__global__ void __launch_bounds__(256) flash_kernel(const float* __restrict__ Q,
                                                    const float* __restrict__ K,
                                                    const float* __restrict__ V,
                                                    float* __restrict__ ctx)
{
    extern __shared__ float sm[];
    float* sQ  = sm;
    float* sK  = sQ + 64*128;
    float* sV  = sK + 64*128;
    float* sS  = sV + 64*128;
    float* s_m  = sS + 64*68;
    float* s_l  = s_m + 64;
    float* s_mn = s_l + 64;
    float* s_sc = s_mn + 64;
    float* s_ps = s_sc + 64;

    const int t  = threadIdx.x;
    const int qi = blockIdx.x;
    const int bh = blockIdx.y;
    const size_t headbase = (size_t)bh * SS * DH;

    const float4* Qg = (const float4*)(Q + headbase + (size_t)qi * 64 * DH);
#pragma unroll
    for (int i = 0; i < 8; i++) {
        int e = i*256 + t;
        int r = e >> 5, c4 = e & 31;
        *(float4*)(sQ + r*128 + c4*4) = Qg[e];
    }
    if (t < 64) { s_m[t] = -1e30f; s_l[t] = 0.f; }

    float o[4][8];
#pragma unroll
    for (int r = 0; r < 4; r++)
#pragma unroll
        for (int c = 0; c < 8; c++) o[r][c] = 0.f;

    const int ti  = t >> 4;
    const int tj  = t & 15;
    const int i0  = ti * 4;
    const int j0s = tj * 4;
    const int j0v = tj * 8;
    const int row = t >> 2;
    const int seg = t & 3;
    const float scale = 0.08838834764831845f;

    for (int kj = 0; kj <= qi; kj++) {
        __syncthreads();
        const float4* Kg = (const float4*)(K + headbase + (size_t)kj * 64 * DH);
        const float4* Vg = (const float4*)(V + headbase + (size_t)kj * 64 * DH);
#pragma unroll
        for (int i = 0; i < 8; i++) {
            int e = i*256 + t;
            int r = e >> 5, c4 = e & 31;
            int sw = c4 ^ ((r >> 2) & 7);
            *(float4*)(sK + r*128 + sw*4) = Kg[e];
            *(float4*)(sV + r*128 + c4*4) = Vg[e];
        }
        __syncthreads();

        float acc[4][4];
#pragma unroll
        for (int r = 0; r < 4; r++)
#pragma unroll
            for (int c = 0; c < 4; c++) acc[r][c] = 0.f;

#pragma unroll 8
        for (int k = 0; k < 128; k += 4) {
            float4 qa[4], kb[4];
#pragma unroll
            for (int r = 0; r < 4; r++)
                qa[r] = *(const float4*)(sQ + (i0+r)*128 + k);
            int chunk = (k >> 2) ^ (tj & 7);
#pragma unroll
            for (int c = 0; c < 4; c++)
                kb[c] = *(const float4*)(sK + (j0s+c)*128 + chunk*4);
#pragma unroll
            for (int r = 0; r < 4; r++)
#pragma unroll
                for (int c = 0; c < 4; c++) {
                    acc[r][c] += qa[r].x * kb[c].x;
                    acc[r][c] += qa[r].y * kb[c].y;
                    acc[r][c] += qa[r].z * kb[c].z;
                    acc[r][c] += qa[r].w * kb[c].w;
                }
        }
#pragma unroll
        for (int r = 0; r < 4; r++)
#pragma unroll
            for (int c = 0; c < 4; c++) {
                float v = acc[r][c] * scale;
                if (kj == qi && (j0s + c) > (i0 + r)) v = -1e30f;
                sS[(i0+r)*68 + j0s + c] = v;
            }
        __syncthreads();

        float mold = s_m[row];
        float rmax = -1e30f;
#pragma unroll 16
        for (int j = 0; j < 64; j++) rmax = fmaxf(rmax, sS[row*68 + j]);
        float mnew = fmaxf(mold, rmax);
        float part = 0.f;
#pragma unroll
        for (int j = seg*16; j < seg*16 + 16; j++) {
            float p = __expf(sS[row*68 + j] - mnew);
            sS[row*68 + j] = p;
            part += p;
        }
        s_ps[row*4 + seg] = part;
        if (seg == 0) { s_mn[row] = mnew; s_sc[row] = __expf(mold - mnew); }
        __syncthreads();
        if (t < 64) {
            s_l[t] = s_l[t] * s_sc[t]
                   + s_ps[t*4] + s_ps[t*4+1] + s_ps[t*4+2] + s_ps[t*4+3];
            s_m[t] = s_mn[t];
        }

#pragma unroll
        for (int r = 0; r < 4; r++) {
            float sc = s_sc[i0 + r];
#pragma unroll
            for (int c = 0; c < 8; c++) o[r][c] *= sc;
        }
#pragma unroll 4
        for (int kk = 0; kk < 64; kk += 4) {
            float4 p[4];
#pragma unroll
            for (int r = 0; r < 4; r++)
                p[r] = *(const float4*)(sS + (i0+r)*68 + kk);
#pragma unroll
            for (int u = 0; u < 4; u++) {
                float4 va = *(const float4*)(sV + (kk+u)*128 + j0v);
                float4 vb = *(const float4*)(sV + (kk+u)*128 + j0v + 4);
#pragma unroll
                for (int r = 0; r < 4; r++) {
                    float pr = (u == 0) ? p[r].x : (u == 1) ? p[r].y
                             : (u == 2) ? p[r].z : p[r].w;
                    o[r][0] += pr * va.x; o[r][1] += pr * va.y;
                    o[r][2] += pr * va.z; o[r][3] += pr * va.w;
                    o[r][4] += pr * vb.x; o[r][5] += pr * vb.y;
                    o[r][6] += pr * vb.z; o[r][7] += pr * vb.w;
                }
            }
        }
    }

    __syncthreads();
    const int b = bh / NH, h = bh % NH;
#pragma unroll
    for (int r = 0; r < 4; r++) {
        float inv = 1.f / s_l[i0 + r];
        int srow = qi*64 + i0 + r;
        float* dst = ctx + ((size_t)(b*SS + srow)) * NPROJ + h*DH + j0v;
        float4 w0, w1;
        w0.x = o[r][0]*inv; w0.y = o[r][1]*inv; w0.z = o[r][2]*inv; w0.w = o[r][3]*inv;
        w1.x = o[r][4]*inv; w1.y = o[r][5]*inv; w1.z = o[r][6]*inv; w1.w = o[r][7]*inv;
        *(float4*)(dst)     = w0;
        *(float4*)(dst + 4) = w1;
    }
}

// ---------------- launch ----------------
extern "C" void kernel_launch(void* const* d_in, const int* in_sizes, int n_in,
                              void* d_out, int out_size)
{
    const float* x  = (const float*)d_in[0];
    const float* Wq = (const float*)d_in[1];
    const float* bq = (const float*)d_in[2];
    const float* Wk = (const float*)d_in[3];
    const float* bk = (const float*)d_in[4];
    const float* Wv = (const float*)d_in[5];
    const float* bv = (const float*)d_in[6];
    const float* Wo = (const float*)d_in[7];
    const float* bo = (const float*)d_in[8];
    float* out = (float*)d_out;

    float *qp, *kp, *vp, *cp;
    cudaGetSymbolAddress((void**)&qp, g_q);
    cudaGetSymbolAddress((void**)&kp, g_k);
    cudaGetSymbolAddress((void**)&vp, g_v);
    cudaGetSymbolAddress((void**)&cp, g_ctx);
    __nv_bfloat16 *xh, *xl, *ch, *cl;
    cudaGetSymbolAddress((void**)&xh, g_xh);
    cudaGetSymbolAddress((void**)&xl, g_xl);
    cudaGetSymbolAddress((void**)&ch, g_ch);
    cudaGetSymbolAddress((void**)&cl, g_cl);
    __nv_bfloat16 *wqh, *wql, *wkh, *wkl, *wvh, *wvl, *woh, *wol;
    cudaGetSymbolAddress((void**)&wqh, g_wqh);
    cudaGetSymbolAddress((void**)&wql, g_wql);
    cudaGetSymbolAddress((void**)&wkh, g_wkh);
    cudaGetSymbolAddress((void**)&wkl, g_wkl);
    cudaGetSymbolAddress((void**)&wvh, g_wvh);
    cudaGetSymbolAddress((void**)&wvl, g_wvl);
    cudaGetSymbolAddress((void**)&woh, g_woh);
    cudaGetSymbolAddress((void**)&wol, g_wol);

    cudaFuncSetAttribute(gemm_mma<0>, cudaFuncAttributeMaxDynamicSharedMemorySize, GEMM_SMEM);
    cudaFuncSetAttribute(gemm_mma<1>, cudaFuncAttributeMaxDynamicSharedMemorySize, GEMM_SMEM);
    const int fa_smem = FA_SMEM_FLOATS * sizeof(float);
    cudaFuncSetAttribute(flash_kernel, cudaFuncAttributeMaxDynamicSharedMemorySize, fa_smem);

    const int n4x = (MTOT * D_MODEL) / 4;
    cvt_hilo<<<(n4x + 255) / 256, 256>>>(x, xh, xl, n4x);
    dim3 tgrid(D_MODEL / 32, D_MODEL / 32);
    transcvt<<<tgrid, 256>>>(Wq, wqh, wql);
    transcvt<<<tgrid, 256>>>(Wk, wkh, wkl);
    transcvt<<<tgrid, 256>>>(Wv, wvh, wvl);
    transcvt<<<tgrid, 256>>>(Wo, woh, wol);

    dim3 ggrid(NPROJ / 128, MTOT / 128);   // (16, 32)
    gemm_mma<0><<<ggrid, 256, GEMM_SMEM>>>(xh, xl, wqh, wql, bq, qp, MTOT, NPROJ, D_MODEL);
    gemm_mma<0><<<ggrid, 256, GEMM_SMEM>>>(xh, xl, wkh, wkl, bk, kp, MTOT, NPROJ, D_MODEL);
    gemm_mma<0><<<ggrid, 256, GEMM_SMEM>>>(xh, xl, wvh, wvl, bv, vp, MTOT, NPROJ, D_MODEL);

    dim3 fgrid(SS / 64, BB * NH);
    flash_kernel<<<fgrid, 256, fa_smem>>>(qp, kp, vp, cp);

    cvt_hilo<<<(n4x + 255) / 256, 256>>>(cp, ch, cl, n4x);
    gemm_mma<1><<<ggrid, 256, GEMM_SMEM>>>(ch, cl, woh, wol, bo, out, MTOT, D_MODEL, D_MODEL);
}

// round 4
// speedup vs baseline: 2.8650x; 1.5598x over previous
#include <cuda_runtime.h>
#include <cuda_bf16.h>
#include <cstdint>
#include <math.h>

#define D_MODEL 2048
#define NH 16
#define DH 128
#define BB 2
#define SS 2048
#define MTOT (BB*SS)      /* 4096 */
#define NPROJ (NH*DH)     /* 2048 */

// ---------------- scratch (bf16 hi/lo everywhere) ----------------
__device__ __nv_bfloat16 g_xh[(size_t)MTOT*D_MODEL];
__device__ __nv_bfloat16 g_xl[(size_t)MTOT*D_MODEL];
__device__ __nv_bfloat16 g_qh[(size_t)BB*NH*SS*DH];
__device__ __nv_bfloat16 g_ql[(size_t)BB*NH*SS*DH];
__device__ __nv_bfloat16 g_kh[(size_t)BB*NH*SS*DH];
__device__ __nv_bfloat16 g_kl[(size_t)BB*NH*SS*DH];
__device__ __nv_bfloat16 g_vh[(size_t)BB*NH*DH*SS];   // transposed [b,h,d,s]
__device__ __nv_bfloat16 g_vl[(size_t)BB*NH*DH*SS];
__device__ __nv_bfloat16 g_ch[(size_t)MTOT*NPROJ];
__device__ __nv_bfloat16 g_cl[(size_t)MTOT*NPROJ];
__device__ __nv_bfloat16 g_wqh[(size_t)D_MODEL*NPROJ];
__device__ __nv_bfloat16 g_wql[(size_t)D_MODEL*NPROJ];
__device__ __nv_bfloat16 g_wkh[(size_t)D_MODEL*NPROJ];
__device__ __nv_bfloat16 g_wkl[(size_t)D_MODEL*NPROJ];
__device__ __nv_bfloat16 g_wvh[(size_t)D_MODEL*NPROJ];
__device__ __nv_bfloat16 g_wvl[(size_t)D_MODEL*NPROJ];
__device__ __nv_bfloat16 g_woh[(size_t)D_MODEL*NPROJ];
__device__ __nv_bfloat16 g_wol[(size_t)D_MODEL*NPROJ];

// ---------------- helpers ----------------
__device__ __forceinline__ uint32_t smem_u32(const void* p) {
    uint32_t a;
    asm("{ .reg .u64 t; cvta.to.shared.u64 t, %1; cvt.u32.u64 %0, t; }" : "=r"(a) : "l"(p));
    return a;
}
#define CP_ASYNC16(dst, src) \
    asm volatile("cp.async.cg.shared.global [%0], [%1], 16;" :: "r"(dst), "l"(src))
#define CP_COMMIT() asm volatile("cp.async.commit_group;" ::: "memory")
#define CP_WAIT1() asm volatile("cp.async.wait_group 1;" ::: "memory")
#define CP_WAIT0() asm volatile("cp.async.wait_group 0;" ::: "memory")

__device__ __forceinline__ void mma_bf16(float* c, uint32_t a0, uint32_t a1,
                                         uint32_t a2, uint32_t a3,
                                         uint32_t b0, uint32_t b1) {
    asm volatile(
        "mma.sync.aligned.m16n8k16.row.col.f32.bf16.bf16.f32 "
        "{%0,%1,%2,%3}, {%4,%5,%6,%7}, {%8,%9}, {%0,%1,%2,%3};"
        : "+f"(c[0]), "+f"(c[1]), "+f"(c[2]), "+f"(c[3])
        : "r"(a0), "r"(a1), "r"(a2), "r"(a3), "r"(b0), "r"(b1));
}
__device__ __forceinline__ uint32_t pack_bf16x2(float lo, float hi) {
    uint32_t r;
    asm("cvt.rn.bf16x2.f32 %0, %1, %2;" : "=r"(r) : "f"(hi), "f"(lo));
    return r;
}
__device__ __forceinline__ void split2(float x, float y, uint32_t& h2, uint32_t& l2) {
    float xh = __bfloat162float(__float2bfloat16(x));
    float yh = __bfloat162float(__float2bfloat16(y));
    h2 = pack_bf16x2(xh, yh);
    l2 = pack_bf16x2(x - xh, y - yh);
}

// ---------------- conversion kernels ----------------
__global__ void __launch_bounds__(256) cvt_hilo(const float* __restrict__ src,
                                                __nv_bfloat16* __restrict__ hi,
                                                __nv_bfloat16* __restrict__ lo, int n4)
{
    int i = blockIdx.x * 256 + threadIdx.x;
    if (i >= n4) return;
    float4 v = ((const float4*)src)[i];
    uint32_t h0, l0, h1, l1;
    split2(v.x, v.y, h0, l0);
    split2(v.z, v.w, h1, l1);
    ((uint32_t*)hi)[i*2]   = h0;
    ((uint32_t*)hi)[i*2+1] = h1;
    ((uint32_t*)lo)[i*2]   = l0;
    ((uint32_t*)lo)[i*2+1] = l1;
}

// W[K][N] -> Wt hi/lo [N][K]
__global__ void __launch_bounds__(256) transcvt(const float* __restrict__ W,
                                                __nv_bfloat16* __restrict__ th,
                                                __nv_bfloat16* __restrict__ tl)
{
    __shared__ float tile[32][33];
    int nb = blockIdx.x * 32, kb = blockIdx.y * 32;
    int tx = threadIdx.x & 31, ty = threadIdx.x >> 5;
#pragma unroll
    for (int j = 0; j < 4; j++)
        tile[ty + j*8][tx] = W[(size_t)(kb + ty + j*8) * D_MODEL + nb + tx];
    __syncthreads();
#pragma unroll
    for (int j = 0; j < 4; j++) {
        int n = nb + ty + j*8;
        float v = tile[tx][ty + j*8];
        __nv_bfloat16 h = __float2bfloat16(v);
        __nv_bfloat16 l = __float2bfloat16(v - __bfloat162float(h));
        th[(size_t)n * D_MODEL + kb + tx] = h;
        tl[(size_t)n * D_MODEL + kb + tx] = l;
    }
}

// ---------------- tensor-core GEMM via mma.sync ----------------
// MODE 0: bf16 hi/lo out, scatter [b,h,s,d].  MODE 1: fp32 row-major.
// MODE 2: bf16 hi/lo out, transposed scatter [b,h,d,s].
#define OFF_AH 0
#define OFF_AL 8192
#define OFF_BH 16384
#define OFF_BL 24576
#define BUF_STRIDE 32768
#define GEMM_SMEM (2*BUF_STRIDE)

__device__ __forceinline__ int swzoff(int row, int ch) {
    return row * 64 + (((ch ^ (row >> 1)) & 3) * 16);
}

template<int MODE>
__global__ void __launch_bounds__(256) gemm_mma(const __nv_bfloat16* __restrict__ Ah,
                                                const __nv_bfloat16* __restrict__ Al,
                                                const __nv_bfloat16* __restrict__ Bh,
                                                const __nv_bfloat16* __restrict__ Bl,
                                                const float* __restrict__ bias,
                                                float* __restrict__ Cf,
                                                __nv_bfloat16* __restrict__ Coh,
                                                __nv_bfloat16* __restrict__ Col,
                                                int M, int N, int K)
{
    extern __shared__ char smb[];
    const uint32_t sb = smem_u32(smb);
    const int t = threadIdx.x;
    const int lane = t & 31;
    const int wid = t >> 5;
    const int g = lane >> 2;
    const int tid4 = lane & 3;
    const int warp_m = wid >> 2;
    const int warp_n = wid & 3;
    const int bm = blockIdx.y * 128, bn = blockIdx.x * 128;

    const int lr = t >> 2;
    const int lc = t & 3;
    const int iters = K >> 5;

    float acc[4][4][4];
#pragma unroll
    for (int a = 0; a < 4; a++)
#pragma unroll
        for (int b = 0; b < 4; b++)
#pragma unroll
            for (int c = 0; c < 4; c++) acc[a][b][c] = 0.f;

    auto issue = [&](int it, int buf) {
        const size_t koff = (size_t)it * 32 + lc * 8;
        const uint32_t bufb = sb + buf * BUF_STRIDE;
#pragma unroll
        for (int i = 0; i < 2; i++) {
            int r = lr + i * 64;
            uint32_t d = bufb + swzoff(r, lc);
            CP_ASYNC16(d + OFF_AH, Ah + (size_t)(bm + r) * K + koff);
            CP_ASYNC16(d + OFF_AL, Al + (size_t)(bm + r) * K + koff);
            CP_ASYNC16(d + OFF_BH, Bh + (size_t)(bn + r) * K + koff);
            CP_ASYNC16(d + OFF_BL, Bl + (size_t)(bn + r) * K + koff);
        }
    };

    issue(0, 0);
    CP_COMMIT();

    for (int it = 0; it < iters; it++) {
        const int buf = it & 1;
        if (it + 1 < iters) { issue(it + 1, buf ^ 1); CP_COMMIT(); CP_WAIT1(); }
        else                { CP_WAIT0(); }
        __syncthreads();

        const char* cb = smb + buf * BUF_STRIDE;
#pragma unroll
        for (int ks = 0; ks < 2; ks++) {
            const int ch0 = ks * 2;
            uint32_t afr[4][4], bhf[4][2], blf[4][2];
#pragma unroll
            for (int mf = 0; mf < 4; mf++) {
                int r0 = warp_m * 64 + mf * 16 + g;
                afr[mf][0] = *(const uint32_t*)(cb + OFF_AH + swzoff(r0, ch0) + tid4*4);
                afr[mf][1] = *(const uint32_t*)(cb + OFF_AH + swzoff(r0+8, ch0) + tid4*4);
                afr[mf][2] = *(const uint32_t*)(cb + OFF_AH + swzoff(r0, ch0+1) + tid4*4);
                afr[mf][3] = *(const uint32_t*)(cb + OFF_AH + swzoff(r0+8, ch0+1) + tid4*4);
            }
#pragma unroll
            for (int nf = 0; nf < 4; nf++) {
                int rb = warp_n * 32 + nf * 8 + g;
                bhf[nf][0] = *(const uint32_t*)(cb + OFF_BH + swzoff(rb, ch0) + tid4*4);
                bhf[nf][1] = *(const uint32_t*)(cb + OFF_BH + swzoff(rb, ch0+1) + tid4*4);
                blf[nf][0] = *(const uint32_t*)(cb + OFF_BL + swzoff(rb, ch0) + tid4*4);
                blf[nf][1] = *(const uint32_t*)(cb + OFF_BL + swzoff(rb, ch0+1) + tid4*4);
            }
#pragma unroll
            for (int mf = 0; mf < 4; mf++)
#pragma unroll
                for (int nf = 0; nf < 4; nf++) {
                    mma_bf16(acc[mf][nf], afr[mf][0], afr[mf][1], afr[mf][2], afr[mf][3],
                             bhf[nf][0], bhf[nf][1]);
                    mma_bf16(acc[mf][nf], afr[mf][0], afr[mf][1], afr[mf][2], afr[mf][3],
                             blf[nf][0], blf[nf][1]);
                }
#pragma unroll
            for (int mf = 0; mf < 4; mf++) {
                int r0 = warp_m * 64 + mf * 16 + g;
                afr[mf][0] = *(const uint32_t*)(cb + OFF_AL + swzoff(r0, ch0) + tid4*4);
                afr[mf][1] = *(const uint32_t*)(cb + OFF_AL + swzoff(r0+8, ch0) + tid4*4);
                afr[mf][2] = *(const uint32_t*)(cb + OFF_AL + swzoff(r0, ch0+1) + tid4*4);
                afr[mf][3] = *(const uint32_t*)(cb + OFF_AL + swzoff(r0+8, ch0+1) + tid4*4);
            }
#pragma unroll
            for (int mf = 0; mf < 4; mf++)
#pragma unroll
                for (int nf = 0; nf < 4; nf++)
                    mma_bf16(acc[mf][nf], afr[mf][0], afr[mf][1], afr[mf][2], afr[mf][3],
                             bhf[nf][0], bhf[nf][1]);
        }
        __syncthreads();
    }

    // ---- epilogue ----
#pragma unroll
    for (int nf = 0; nf < 4; nf++) {
        const int n = bn + warp_n * 32 + nf * 8 + tid4 * 2;
        const float2 bv = *(const float2*)(bias + n);
#pragma unroll
        for (int mf = 0; mf < 4; mf++) {
#pragma unroll
            for (int half = 0; half < 2; half++) {
                const int m = bm + warp_m * 64 + mf * 16 + g + half * 8;
                float wx = acc[mf][nf][half*2 + 0] + bv.x;
                float wy = acc[mf][nf][half*2 + 1] + bv.y;
                if (MODE == 1) {
                    float2 w; w.x = wx; w.y = wy;
                    *(float2*)(Cf + (size_t)m * N + n) = w;
                } else if (MODE == 0) {
                    int b = m >> 11, s = m & (SS - 1), h = n >> 7, d = n & (DH - 1);
                    size_t idx = (((size_t)(b * NH + h)) * SS + s) * DH + d;
                    uint32_t h2, l2;
                    split2(wx, wy, h2, l2);
                    *(uint32_t*)(Coh + idx) = h2;
                    *(uint32_t*)(Col + idx) = l2;
                } else {  // MODE 2: V transposed [b,h,d,s]
                    int b = m >> 11, s = m & (SS - 1), h = n >> 7, d = n & (DH - 1);
                    size_t i0 = (((size_t)(b * NH + h)) * DH + d) * SS + s;
                    __nv_bfloat16 hx = __float2bfloat16(wx);
                    __nv_bfloat16 hy = __float2bfloat16(wy);
                    Coh[i0]      = hx;
                    Coh[i0 + SS] = hy;
                    Col[i0]      = __float2bfloat16(wx - __bfloat162float(hx));
                    Col[i0 + SS] = __float2bfloat16(wy - __bfloat162float(hy));
                }
            }
        }
    }
}

// ---------------- Flash attention on tensor cores ----------------
// Br=Bc=64, d=128, 128 threads (4 warps, each 16 q-rows).
#define FQH 0
#define FQL 16384
#define FKH 32768
#define FKL 49152
#define FVH 65536
#define FVL 81920
#define FA_SMEM 98304

__device__ __forceinline__ uint32_t sw256(int r, int byteoff) {
    int c = byteoff >> 4;
    int sc = c ^ (r & 7);
    return (uint32_t)(r * 256 + sc * 16 + (byteoff & 15));
}
__device__ __forceinline__ uint32_t sw128(int r, int byteoff) {
    int c = byteoff >> 4;
    int sc = c ^ (r & 7);
    return (uint32_t)(r * 128 + sc * 16 + (byteoff & 15));
}

__global__ void __launch_bounds__(128) flash_mma(
    const __nv_bfloat16* __restrict__ Qh, const __nv_bfloat16* __restrict__ Ql,
    const __nv_bfloat16* __restrict__ Kh, const __nv_bfloat16* __restrict__ Kl,
    const __nv_bfloat16* __restrict__ Vh, const __nv_bfloat16* __restrict__ Vl,
    __nv_bfloat16* __restrict__ Ch, __nv_bfloat16* __restrict__ Cl)
{
    extern __shared__ char smb[];
    const uint32_t sb = smem_u32(smb);
    const int t = threadIdx.x;
    const int lane = t & 31, w = t >> 5;
    const int g = lane >> 2, t4 = lane & 3;
    const int qi = blockIdx.x, bh = blockIdx.y;
    const size_t hb = (size_t)bh * SS * DH;   // same stride for [s,d] and [d,s]

    // Q tile (hi+lo): 64 rows x 16 chunks of 16B, x2
    {
        const __nv_bfloat16* qbh = Qh + hb + (size_t)qi * 64 * DH;
        const __nv_bfloat16* qbl = Ql + hb + (size_t)qi * 64 * DH;
#pragma unroll
        for (int i = 0; i < 8; i++) {
            int id = t + i * 128;
            int r = id >> 4, c = id & 15;
            uint32_t sw = sw256(r, c * 16);
            CP_ASYNC16(sb + FQH + sw, qbh + (size_t)r * DH + c * 8);
            CP_ASYNC16(sb + FQL + sw, qbl + (size_t)r * DH + c * 8);
        }
    }
    CP_COMMIT();

    float o[16][4];
#pragma unroll
    for (int i = 0; i < 16; i++)
#pragma unroll
        for (int j = 0; j < 4; j++) o[i][j] = 0.f;
    float m0 = -1e30f, m1 = -1e30f, l0 = 0.f, l1 = 0.f;

    const int qr0 = w * 16 + g;     // local q row (0..63)
    const float scale = 0.08838834764831845f;

    for (int kj = 0; kj <= qi; kj++) {
        __syncthreads();   // all warps done with previous K/V smem
        {
            const __nv_bfloat16* kbh = Kh + hb + (size_t)kj * 64 * DH;
            const __nv_bfloat16* kbl = Kl + hb + (size_t)kj * 64 * DH;
#pragma unroll
            for (int i = 0; i < 8; i++) {
                int id = t + i * 128;
                int r = id >> 4, c = id & 15;
                uint32_t sw = sw256(r, c * 16);
                CP_ASYNC16(sb + FKH + sw, kbh + (size_t)r * DH + c * 8);
                CP_ASYNC16(sb + FKL + sw, kbl + (size_t)r * DH + c * 8);
            }
            const __nv_bfloat16* vbh = Vh + hb + (size_t)kj * 64;
            const __nv_bfloat16* vbl = Vl + hb + (size_t)kj * 64;
#pragma unroll
            for (int i = 0; i < 8; i++) {
                int id = t + i * 128;
                int r = id >> 3, c = id & 7;   // 128 rows (d) x 8 chunks (kv)
                uint32_t sw = sw128(r, c * 16);
                CP_ASYNC16(sb + FVH + sw, vbh + (size_t)r * SS + c * 8);
                CP_ASYNC16(sb + FVL + sw, vbl + (size_t)r * SS + c * 8);
            }
        }
        CP_COMMIT(); CP_WAIT0();
        __syncthreads();

        // ---- S = Q K^T (hi/lo compensated) ----
        float s[8][4];
#pragma unroll
        for (int nt = 0; nt < 8; nt++)
#pragma unroll
            for (int j = 0; j < 4; j++) s[nt][j] = 0.f;

#pragma unroll
        for (int kt = 0; kt < 8; kt++) {
            const int bo = kt * 32 + t4 * 4;   // byte offset in 256B row
            uint32_t aqh[4], aql[4];
            aqh[0] = *(const uint32_t*)(smb + FQH + sw256(qr0,     bo));
            aqh[1] = *(const uint32_t*)(smb + FQH + sw256(qr0 + 8, bo));
            aqh[2] = *(const uint32_t*)(smb + FQH + sw256(qr0,     bo + 16));
            aqh[3] = *(const uint32_t*)(smb + FQH + sw256(qr0 + 8, bo + 16));
            aql[0] = *(const uint32_t*)(smb + FQL + sw256(qr0,     bo));
            aql[1] = *(const uint32_t*)(smb + FQL + sw256(qr0 + 8, bo));
            aql[2] = *(const uint32_t*)(smb + FQL + sw256(qr0,     bo + 16));
            aql[3] = *(const uint32_t*)(smb + FQL + sw256(qr0 + 8, bo + 16));
#pragma unroll
            for (int nt = 0; nt < 8; nt++) {
                const int kr = nt * 8 + g;
                uint32_t b0h = *(const uint32_t*)(smb + FKH + sw256(kr, bo));
                uint32_t b1h = *(const uint32_t*)(smb + FKH + sw256(kr, bo + 16));
                uint32_t b0l = *(const uint32_t*)(smb + FKL + sw256(kr, bo));
                uint32_t b1l = *(const uint32_t*)(smb + FKL + sw256(kr, bo + 16));
                mma_bf16(s[nt], aqh[0], aqh[1], aqh[2], aqh[3], b0h, b1h);
                mma_bf16(s[nt], aqh[0], aqh[1], aqh[2], aqh[3], b0l, b1l);
                mma_bf16(s[nt], aql[0], aql[1], aql[2], aql[3], b0h, b1h);
            }
        }

        // scale + causal mask (diagonal tile only)
#pragma unroll
        for (int nt = 0; nt < 8; nt++)
#pragma unroll
            for (int j = 0; j < 4; j++) s[nt][j] *= scale;
        if (kj == qi) {
#pragma unroll
            for (int nt = 0; nt < 8; nt++) {
                int c0 = nt * 8 + 2 * t4;
                if (c0     > qr0)     s[nt][0] = -1e30f;
                if (c0 + 1 > qr0)     s[nt][1] = -1e30f;
                if (c0     > qr0 + 8) s[nt][2] = -1e30f;
                if (c0 + 1 > qr0 + 8) s[nt][3] = -1e30f;
            }
        }

        // ---- online softmax (rows g, g+8) ----
        float rm0 = -1e30f, rm1 = -1e30f;
#pragma unroll
        for (int nt = 0; nt < 8; nt++) {
            rm0 = fmaxf(rm0, fmaxf(s[nt][0], s[nt][1]));
            rm1 = fmaxf(rm1, fmaxf(s[nt][2], s[nt][3]));
        }
        rm0 = fmaxf(rm0, __shfl_xor_sync(0xffffffff, rm0, 1));
        rm0 = fmaxf(rm0, __shfl_xor_sync(0xffffffff, rm0, 2));
        rm1 = fmaxf(rm1, __shfl_xor_sync(0xffffffff, rm1, 1));
        rm1 = fmaxf(rm1, __shfl_xor_sync(0xffffffff, rm1, 2));
        float mn0 = fmaxf(m0, rm0), mn1 = fmaxf(m1, rm1);
        float al0 = __expf(m0 - mn0), al1 = __expf(m1 - mn1);
        float ls0 = 0.f, ls1 = 0.f;
#pragma unroll
        for (int nt = 0; nt < 8; nt++) {
            s[nt][0] = __expf(s[nt][0] - mn0);
            s[nt][1] = __expf(s[nt][1] - mn0);
            s[nt][2] = __expf(s[nt][2] - mn1);
            s[nt][3] = __expf(s[nt][3] - mn1);
            ls0 += s[nt][0] + s[nt][1];
            ls1 += s[nt][2] + s[nt][3];
        }
        ls0 += __shfl_xor_sync(0xffffffff, ls0, 1);
        ls0 += __shfl_xor_sync(0xffffffff, ls0, 2);
        ls1 += __shfl_xor_sync(0xffffffff, ls1, 1);
        ls1 += __shfl_xor_sync(0xffffffff, ls1, 2);
        l0 = l0 * al0 + ls0;  m0 = mn0;
        l1 = l1 * al1 + ls1;  m1 = mn1;
#pragma unroll
        for (int ntc = 0; ntc < 16; ntc++) {
            o[ntc][0] *= al0; o[ntc][1] *= al0;
            o[ntc][2] *= al1; o[ntc][3] *= al1;
        }

        // ---- PV: ctx += P V  (P in regs re-used as A fragment) ----
#pragma unroll
        for (int kt = 0; kt < 4; kt++) {
            uint32_t aph[4], apl[4];
            {
                float p00 = s[2*kt][0],   p01 = s[2*kt][1];
                float p10 = s[2*kt][2],   p11 = s[2*kt][3];
                float p20 = s[2*kt+1][0], p21 = s[2*kt+1][1];
                float p30 = s[2*kt+1][2], p31 = s[2*kt+1][3];
                split2(p00, p01, aph[0], apl[0]);
                split2(p10, p11, aph[1], apl[1]);
                split2(p20, p21, aph[2], apl[2]);
                split2(p30, p31, aph[3], apl[3]);
            }
            const int bo = kt * 32 + t4 * 4;   // byte offset in 128B Vt row
#pragma unroll
            for (int ntc = 0; ntc < 16; ntc++) {
                const int vr = ntc * 8 + g;
                uint32_t b0h = *(const uint32_t*)(smb + FVH + sw128(vr, bo));
                uint32_t b1h = *(const uint32_t*)(smb + FVH + sw128(vr, bo + 16));
                uint32_t b0l = *(const uint32_t*)(smb + FVL + sw128(vr, bo));
                uint32_t b1l = *(const uint32_t*)(smb + FVL + sw128(vr, bo + 16));
                mma_bf16(o[ntc], aph[0], aph[1], aph[2], aph[3], b0h, b1h);
                mma_bf16(o[ntc], aph[0], aph[1], aph[2], aph[3], b0l, b1l);
                mma_bf16(o[ntc], apl[0], apl[1], apl[2], apl[3], b0h, b1h);
            }
        }
    }

    // ---- epilogue: normalize, split hi/lo, store ctx [b,s, h*128+d] ----
    const float inv0 = 1.f / l0, inv1 = 1.f / l1;
    const int b = bh >> 4, h = bh & 15;
    const int row0 = qi * 64 + qr0;
#pragma unroll
    for (int ntc = 0; ntc < 16; ntc++) {
        const int col = h * 128 + ntc * 8 + 2 * t4;
        size_t i0 = ((size_t)(b * SS + row0)) * NPROJ + col;
        size_t i1 = ((size_t)(b * SS + row0 + 8)) * NPROJ + col;
        uint32_t h2, l2;
        split2(o[ntc][0] * inv0, o[ntc][1] * inv0, h2, l2);
        *(uint32_t*)(Ch + i0) = h2;
        *(uint32_t*)(Cl + i0) = l2;
        split2(o[ntc][2] * inv1, o[ntc][3] * inv1, h2, l2);
        *(uint32_t*)(Ch + i1) = h2;
        *(uint32_t*)(Cl + i1) = l2;
    }
}

// ---------------- launch ----------------
extern "C" void kernel_launch(void* const* d_in, const int* in_sizes, int n_in,
                              void* d_out, int out_size)
{
    const float* x  = (const float*)d_in[0];
    const float* Wq = (const float*)d_in[1];
    const float* bq = (const float*)d_in[2];
    const float* Wk = (const float*)d_in[3];
    const float* bk = (const float*)d_in[4];
    const float* Wv = (const float*)d_in[5];
    const float* bv = (const float*)d_in[6];
    const float* Wo = (const float*)d_in[7];
    const float* bo = (const float*)d_in[8];
    float* out = (float*)d_out;

    __nv_bfloat16 *xh, *xl, *ch, *cl, *qh, *ql, *kh, *kl, *vh, *vl;
    cudaGetSymbolAddress((void**)&xh, g_xh);
    cudaGetSymbolAddress((void**)&xl, g_xl);
    cudaGetSymbolAddress((void**)&ch, g_ch);
    cudaGetSymbolAddress((void**)&cl, g_cl);
    cudaGetSymbolAddress((void**)&qh, g_qh);
    cudaGetSymbolAddress((void**)&ql, g_ql);
    cudaGetSymbolAddress((void**)&kh, g_kh);
    cudaGetSymbolAddress((void**)&kl, g_kl);
    cudaGetSymbolAddress((void**)&vh, g_vh);
    cudaGetSymbolAddress((void**)&vl, g_vl);
    __nv_bfloat16 *wqh, *wql, *wkh, *wkl, *wvh, *wvl, *woh, *wol;
    cudaGetSymbolAddress((void**)&wqh, g_wqh);
    cudaGetSymbolAddress((void**)&wql, g_wql);
    cudaGetSymbolAddress((void**)&wkh, g_wkh);
    cudaGetSymbolAddress((void**)&wkl, g_wkl);
    cudaGetSymbolAddress((void**)&wvh, g_wvh);
    cudaGetSymbolAddress((void**)&wvl, g_wvl);
    cudaGetSymbolAddress((void**)&woh, g_woh);
    cudaGetSymbolAddress((void**)&wol, g_wol);

    cudaFuncSetAttribute(gemm_mma<0>, cudaFuncAttributeMaxDynamicSharedMemorySize, GEMM_SMEM);
    cudaFuncSetAttribute(gemm_mma<1>, cudaFuncAttributeMaxDynamicSharedMemorySize, GEMM_SMEM);
    cudaFuncSetAttribute(gemm_mma<2>, cudaFuncAttributeMaxDynamicSharedMemorySize, GEMM_SMEM);
    cudaFuncSetAttribute(flash_mma, cudaFuncAttributeMaxDynamicSharedMemorySize, FA_SMEM);

    const int n4x = (MTOT * D_MODEL) / 4;
    cvt_hilo<<<(n4x + 255) / 256, 256>>>(x, xh, xl, n4x);
    dim3 tgrid(D_MODEL / 32, D_MODEL / 32);
    transcvt<<<tgrid, 256>>>(Wq, wqh, wql);
    transcvt<<<tgrid, 256>>>(Wk, wkh, wkl);
    transcvt<<<tgrid, 256>>>(Wv, wvh, wvl);
    transcvt<<<tgrid, 256>>>(Wo, woh, wol);

    dim3 ggrid(NPROJ / 128, MTOT / 128);   // (16, 32)
    gemm_mma<0><<<ggrid, 256, GEMM_SMEM>>>(xh, xl, wqh, wql, bq, nullptr, qh, ql, MTOT, NPROJ, D_MODEL);
    gemm_mma<0><<<ggrid, 256, GEMM_SMEM>>>(xh, xl, wkh, wkl, bk, nullptr, kh, kl, MTOT, NPROJ, D_MODEL);
    gemm_mma<2><<<ggrid, 256, GEMM_SMEM>>>(xh, xl, wvh, wvl, bv, nullptr, vh, vl, MTOT, NPROJ, D_MODEL);

    dim3 fgrid(SS / 64, BB * NH);          // (32, 32)
    flash_mma<<<fgrid, 128, FA_SMEM>>>(qh, ql, kh, kl, vh, vl, ch, cl);

    gemm_mma<1><<<ggrid, 256, GEMM_SMEM>>>(ch, cl, woh, wol, bo, out, nullptr, nullptr, MTOT, D_MODEL, D_MODEL);
}

// round 5
// speedup vs baseline: 3.3950x; 1.1850x over previous
#include <cuda_runtime.h>
#include <cuda_bf16.h>
#include <cstdint>
#include <math.h>

#define D_MODEL 2048
#define NH 16
#define DH 128
#define BB 2
#define SS 2048
#define MTOT (BB*SS)      /* 4096 */
#define NPROJ (NH*DH)     /* 2048 */

// ---------------- scratch (bf16 hi/lo everywhere) ----------------
__device__ __nv_bfloat16 g_xh[(size_t)MTOT*D_MODEL];
__device__ __nv_bfloat16 g_xl[(size_t)MTOT*D_MODEL];
__device__ __nv_bfloat16 g_qh[(size_t)BB*NH*SS*DH];
__device__ __nv_bfloat16 g_ql[(size_t)BB*NH*SS*DH];
__device__ __nv_bfloat16 g_kh[(size_t)BB*NH*SS*DH];
__device__ __nv_bfloat16 g_kl[(size_t)BB*NH*SS*DH];
__device__ __nv_bfloat16 g_vh[(size_t)BB*NH*DH*SS];   // transposed [b,h,d,s]
__device__ __nv_bfloat16 g_vl[(size_t)BB*NH*DH*SS];
__device__ __nv_bfloat16 g_ch[(size_t)MTOT*NPROJ];
__device__ __nv_bfloat16 g_cl[(size_t)MTOT*NPROJ];
__device__ __nv_bfloat16 g_wqh[(size_t)D_MODEL*NPROJ];
__device__ __nv_bfloat16 g_wql[(size_t)D_MODEL*NPROJ];
__device__ __nv_bfloat16 g_wkh[(size_t)D_MODEL*NPROJ];
__device__ __nv_bfloat16 g_wkl[(size_t)D_MODEL*NPROJ];
__device__ __nv_bfloat16 g_wvh[(size_t)D_MODEL*NPROJ];
__device__ __nv_bfloat16 g_wvl[(size_t)D_MODEL*NPROJ];
__device__ __nv_bfloat16 g_woh[(size_t)D_MODEL*NPROJ];
__device__ __nv_bfloat16 g_wol[(size_t)D_MODEL*NPROJ];

// ---------------- helpers ----------------
__device__ __forceinline__ uint32_t smem_u32(const void* p) {
    uint32_t a;
    asm("{ .reg .u64 t; cvta.to.shared.u64 t, %1; cvt.u32.u64 %0, t; }" : "=r"(a) : "l"(p));
    return a;
}
#define CP_ASYNC16(dst, src) \
    asm volatile("cp.async.cg.shared.global [%0], [%1], 16;" :: "r"(dst), "l"(src))
#define CP_COMMIT() asm volatile("cp.async.commit_group;" ::: "memory")
#define CP_WAIT1() asm volatile("cp.async.wait_group 1;" ::: "memory")
#define CP_WAIT0() asm volatile("cp.async.wait_group 0;" ::: "memory")

__device__ __forceinline__ void mma_bf16(float* c, const uint32_t* a,
                                         uint32_t b0, uint32_t b1) {
    asm volatile(
        "mma.sync.aligned.m16n8k16.row.col.f32.bf16.bf16.f32 "
        "{%0,%1,%2,%3}, {%4,%5,%6,%7}, {%8,%9}, {%0,%1,%2,%3};"
        : "+f"(c[0]), "+f"(c[1]), "+f"(c[2]), "+f"(c[3])
        : "r"(a[0]), "r"(a[1]), "r"(a[2]), "r"(a[3]), "r"(b0), "r"(b1));
}
__device__ __forceinline__ void ldsmx4(uint32_t* r, uint32_t addr) {
    asm volatile("ldmatrix.sync.aligned.m8n8.x4.shared.b16 {%0,%1,%2,%3}, [%4];"
                 : "=r"(r[0]), "=r"(r[1]), "=r"(r[2]), "=r"(r[3]) : "r"(addr));
}
__device__ __forceinline__ uint32_t pack_bf16x2(float lo, float hi) {
    uint32_t r;
    asm("cvt.rn.bf16x2.f32 %0, %1, %2;" : "=r"(r) : "f"(hi), "f"(lo));
    return r;
}
__device__ __forceinline__ void split2(float x, float y, uint32_t& h2, uint32_t& l2) {
    float xh = __bfloat162float(__float2bfloat16(x));
    float yh = __bfloat162float(__float2bfloat16(y));
    h2 = pack_bf16x2(xh, yh);
    l2 = pack_bf16x2(x - xh, y - yh);
}

// ---------------- conversion kernels ----------------
__global__ void __launch_bounds__(256) cvt_hilo(const float* __restrict__ src,
                                                __nv_bfloat16* __restrict__ hi,
                                                __nv_bfloat16* __restrict__ lo, int n4)
{
    int i = blockIdx.x * 256 + threadIdx.x;
    if (i >= n4) return;
    float4 v = ((const float4*)src)[i];
    uint32_t h0, l0, h1, l1;
    split2(v.x, v.y, h0, l0);
    split2(v.z, v.w, h1, l1);
    ((uint32_t*)hi)[i*2]   = h0;
    ((uint32_t*)hi)[i*2+1] = h1;
    ((uint32_t*)lo)[i*2]   = l0;
    ((uint32_t*)lo)[i*2+1] = l1;
}

// 4 weights W[K][N] -> Wt hi/lo [N][K], fused via blockIdx.z
__global__ void __launch_bounds__(256) transcvt4(
    const float* __restrict__ W0, const float* __restrict__ W1,
    const float* __restrict__ W2, const float* __restrict__ W3,
    __nv_bfloat16* __restrict__ t0h, __nv_bfloat16* __restrict__ t0l,
    __nv_bfloat16* __restrict__ t1h, __nv_bfloat16* __restrict__ t1l,
    __nv_bfloat16* __restrict__ t2h, __nv_bfloat16* __restrict__ t2l,
    __nv_bfloat16* __restrict__ t3h, __nv_bfloat16* __restrict__ t3l)
{
    const float* W; __nv_bfloat16 *th, *tl;
    switch (blockIdx.z) {
        case 0: W = W0; th = t0h; tl = t0l; break;
        case 1: W = W1; th = t1h; tl = t1l; break;
        case 2: W = W2; th = t2h; tl = t2l; break;
        default: W = W3; th = t3h; tl = t3l; break;
    }
    __shared__ float tile[32][33];
    int nb = blockIdx.x * 32, kb = blockIdx.y * 32;
    int tx = threadIdx.x & 31, ty = threadIdx.x >> 5;
#pragma unroll
    for (int j = 0; j < 4; j++)
        tile[ty + j*8][tx] = W[(size_t)(kb + ty + j*8) * D_MODEL + nb + tx];
    __syncthreads();
#pragma unroll
    for (int j = 0; j < 4; j++) {
        int n = nb + ty + j*8;
        float v = tile[tx][ty + j*8];
        __nv_bfloat16 h = __float2bfloat16(v);
        __nv_bfloat16 l = __float2bfloat16(v - __bfloat162float(h));
        th[(size_t)n * D_MODEL + kb + tx] = h;
        tl[(size_t)n * D_MODEL + kb + tx] = l;
    }
}

// ---------------- GEMM core (ldmatrix + 3-stage cp.async) ----------------
#define OFF_AH 0
#define OFF_AL 8192
#define OFF_BH 16384
#define OFF_BL 24576
#define BUF_STRIDE 32768
#define GEMM_SMEM (3*BUF_STRIDE)

__device__ __forceinline__ int swzoff(int row, int ch) {
    return row * 64 + (((ch ^ (row >> 1)) & 3) * 16);
}

__device__ __forceinline__ void g_issue(const __nv_bfloat16* Ah, const __nv_bfloat16* Al,
                                        const __nv_bfloat16* Bh, const __nv_bfloat16* Bl,
                                        uint32_t sb, int bm, int bn, int K, int t,
                                        int it, int buf)
{
    const int lr = t >> 2, lc = t & 3;
    const size_t koff = (size_t)it * 32 + lc * 8;
    const uint32_t bufb = sb + buf * BUF_STRIDE;
#pragma unroll
    for (int i = 0; i < 2; i++) {
        int r = lr + i * 64;
        uint32_t d = bufb + swzoff(r, lc);
        CP_ASYNC16(d + OFF_AH, Ah + (size_t)(bm + r) * K + koff);
        CP_ASYNC16(d + OFF_AL, Al + (size_t)(bm + r) * K + koff);
        CP_ASYNC16(d + OFF_BH, Bh + (size_t)(bn + r) * K + koff);
        CP_ASYNC16(d + OFF_BL, Bl + (size_t)(bn + r) * K + koff);
    }
}

__device__ __forceinline__ void gemm_core(const __nv_bfloat16* Ah, const __nv_bfloat16* Al,
                                          const __nv_bfloat16* Bh, const __nv_bfloat16* Bl,
                                          uint32_t sb, int bm, int bn, int K,
                                          int t, int lane, int warp_m, int warp_n,
                                          float acc[4][4][4])
{
    const int q8 = lane >> 3, rr = lane & 7;
    const int chqA = q8 >> 1, chqB = q8 & 1;
    int rA64[4], sA[4], rB64[2], sB[2];
#pragma unroll
    for (int mf = 0; mf < 4; mf++) {
        int r = warp_m * 64 + mf * 16 + rr + ((q8 & 1) << 3);
        rA64[mf] = r * 64; sA[mf] = (r >> 1) & 3;
    }
#pragma unroll
    for (int p = 0; p < 2; p++) {
        int r = warp_n * 32 + p * 16 + rr + ((q8 >> 1) << 3);
        rB64[p] = r * 64; sB[p] = (r >> 1) & 3;
    }

    const int iters = K >> 5;
    g_issue(Ah, Al, Bh, Bl, sb, bm, bn, K, t, 0, 0); CP_COMMIT();
    g_issue(Ah, Al, Bh, Bl, sb, bm, bn, K, t, 1, 1); CP_COMMIT();

    int buf = 0;
    for (int it = 0; it < iters; it++) {
        if (it == iters - 1) { CP_WAIT0(); } else { CP_WAIT1(); }
        __syncthreads();
        if (it + 2 < iters) {
            int b2 = buf + 2; if (b2 >= 3) b2 -= 3;
            g_issue(Ah, Al, Bh, Bl, sb, bm, bn, K, t, it + 2, b2);
            CP_COMMIT();
        }
        const uint32_t cb = sb + buf * BUF_STRIDE;
#pragma unroll
        for (int ks = 0; ks < 2; ks++) {
            const int ch0 = ks * 2;
            uint32_t aq[4][4], bh4[2][4], bl4[2][4];
#pragma unroll
            for (int mf = 0; mf < 4; mf++)
                ldsmx4(aq[mf], cb + OFF_AH + rA64[mf] + (((ch0 + chqA) ^ sA[mf]) & 3) * 16);
#pragma unroll
            for (int p = 0; p < 2; p++) {
                ldsmx4(bh4[p], cb + OFF_BH + rB64[p] + (((ch0 + chqB) ^ sB[p]) & 3) * 16);
                ldsmx4(bl4[p], cb + OFF_BL + rB64[p] + (((ch0 + chqB) ^ sB[p]) & 3) * 16);
            }
#pragma unroll
            for (int mf = 0; mf < 4; mf++)
#pragma unroll
                for (int nf = 0; nf < 4; nf++) {
                    const int p = nf >> 1, h = (nf & 1) * 2;
                    mma_bf16(acc[mf][nf], aq[mf], bh4[p][h], bh4[p][h+1]);
                    mma_bf16(acc[mf][nf], aq[mf], bl4[p][h], bl4[p][h+1]);
                }
#pragma unroll
            for (int mf = 0; mf < 4; mf++)
                ldsmx4(aq[mf], cb + OFF_AL + rA64[mf] + (((ch0 + chqA) ^ sA[mf]) & 3) * 16);
#pragma unroll
            for (int mf = 0; mf < 4; mf++)
#pragma unroll
                for (int nf = 0; nf < 4; nf++) {
                    const int p = nf >> 1, h = (nf & 1) * 2;
                    mma_bf16(acc[mf][nf], aq[mf], bh4[p][h], bh4[p][h+1]);
                }
        }
        __syncthreads();
        if (++buf == 3) buf = 0;
    }
}

// fused QKV projections: grid (N/128, M/128, 3)
__global__ void __launch_bounds__(256) gemm_qkv(
    const __nv_bfloat16* __restrict__ xh, const __nv_bfloat16* __restrict__ xl,
    const __nv_bfloat16* __restrict__ wqh, const __nv_bfloat16* __restrict__ wql,
    const __nv_bfloat16* __restrict__ wkh, const __nv_bfloat16* __restrict__ wkl,
    const __nv_bfloat16* __restrict__ wvh, const __nv_bfloat16* __restrict__ wvl,
    const float* __restrict__ bq, const float* __restrict__ bk, const float* __restrict__ bv,
    __nv_bfloat16* __restrict__ qh, __nv_bfloat16* __restrict__ ql,
    __nv_bfloat16* __restrict__ kh, __nv_bfloat16* __restrict__ kl,
    __nv_bfloat16* __restrict__ vh, __nv_bfloat16* __restrict__ vl)
{
    extern __shared__ char smb[];
    const uint32_t sb = smem_u32(smb);
    const int t = threadIdx.x, lane = t & 31, wid = t >> 5;
    const int g = lane >> 2, tid4 = lane & 3;
    const int warp_m = wid >> 2, warp_n = wid & 3;
    const int bm = blockIdx.y * 128, bn = blockIdx.x * 128;
    const int z = blockIdx.z;

    const __nv_bfloat16 *Bh_, *Bl_; const float* bias_;
    __nv_bfloat16 *Oh_, *Ol_;
    if (z == 0)      { Bh_ = wqh; Bl_ = wql; bias_ = bq; Oh_ = qh; Ol_ = ql; }
    else if (z == 1) { Bh_ = wkh; Bl_ = wkl; bias_ = bk; Oh_ = kh; Ol_ = kl; }
    else             { Bh_ = wvh; Bl_ = wvl; bias_ = bv; Oh_ = vh; Ol_ = vl; }

    float acc[4][4][4];
#pragma unroll
    for (int a = 0; a < 4; a++)
#pragma unroll
        for (int b = 0; b < 4; b++)
#pragma unroll
            for (int c = 0; c < 4; c++) acc[a][b][c] = 0.f;

    gemm_core(xh, xl, Bh_, Bl_, sb, bm, bn, D_MODEL, t, lane, warp_m, warp_n, acc);

#pragma unroll
    for (int nf = 0; nf < 4; nf++) {
        const int n = bn + warp_n * 32 + nf * 8 + tid4 * 2;
        const float2 bv2 = *(const float2*)(bias_ + n);
#pragma unroll
        for (int mf = 0; mf < 4; mf++) {
#pragma unroll
            for (int half = 0; half < 2; half++) {
                const int m = bm + warp_m * 64 + mf * 16 + g + half * 8;
                float wx = acc[mf][nf][half*2 + 0] + bv2.x;
                float wy = acc[mf][nf][half*2 + 1] + bv2.y;
                int b = m >> 11, s = m & (SS - 1), h = n >> 7, d = n & (DH - 1);
                if (z < 2) {
                    size_t idx = (((size_t)(b * NH + h)) * SS + s) * DH + d;
                    uint32_t h2, l2;
                    split2(wx, wy, h2, l2);
                    *(uint32_t*)(Oh_ + idx) = h2;
                    *(uint32_t*)(Ol_ + idx) = l2;
                } else {
                    size_t i0 = (((size_t)(b * NH + h)) * DH + d) * SS + s;
                    __nv_bfloat16 hx = __float2bfloat16(wx);
                    __nv_bfloat16 hy = __float2bfloat16(wy);
                    Oh_[i0]      = hx;
                    Oh_[i0 + SS] = hy;
                    Ol_[i0]      = __float2bfloat16(wx - __bfloat162float(hx));
                    Ol_[i0 + SS] = __float2bfloat16(wy - __bfloat162float(hy));
                }
            }
        }
    }
}

// output projection: fp32 row-major out
__global__ void __launch_bounds__(256) gemm_out(
    const __nv_bfloat16* __restrict__ Ah, const __nv_bfloat16* __restrict__ Al,
    const __nv_bfloat16* __restrict__ Bh, const __nv_bfloat16* __restrict__ Bl,
    const float* __restrict__ bias, float* __restrict__ Cf)
{
    extern __shared__ char smb[];
    const uint32_t sb = smem_u32(smb);
    const int t = threadIdx.x, lane = t & 31, wid = t >> 5;
    const int g = lane >> 2, tid4 = lane & 3;
    const int warp_m = wid >> 2, warp_n = wid & 3;
    const int bm = blockIdx.y * 128, bn = blockIdx.x * 128;

    float acc[4][4][4];
#pragma unroll
    for (int a = 0; a < 4; a++)
#pragma unroll
        for (int b = 0; b < 4; b++)
#pragma unroll
            for (int c = 0; c < 4; c++) acc[a][b][c] = 0.f;

    gemm_core(Ah, Al, Bh, Bl, sb, bm, bn, D_MODEL, t, lane, warp_m, warp_n, acc);

#pragma unroll
    for (int nf = 0; nf < 4; nf++) {
        const int n = bn + warp_n * 32 + nf * 8 + tid4 * 2;
        const float2 bv2 = *(const float2*)(bias + n);
#pragma unroll
        for (int mf = 0; mf < 4; mf++) {
#pragma unroll
            for (int half = 0; half < 2; half++) {
                const int m = bm + warp_m * 64 + mf * 16 + g + half * 8;
                float2 w;
                w.x = acc[mf][nf][half*2 + 0] + bv2.x;
                w.y = acc[mf][nf][half*2 + 1] + bv2.y;
                *(float2*)(Cf + (size_t)m * D_MODEL + n) = w;
            }
        }
    }
}

// ---------------- Flash attention (tensor cores + ldmatrix) ----------------
#define FQH 0
#define FQL 16384
#define FKH 32768
#define FKL 49152
#define FVH 65536
#define FVL 81920
#define FA_SMEM 98304

__device__ __forceinline__ uint32_t sw256(int r, int byteoff) {
    int c = byteoff >> 4;
    int sc = c ^ (r & 7);
    return (uint32_t)(r * 256 + sc * 16 + (byteoff & 15));
}
__device__ __forceinline__ uint32_t sw128(int r, int byteoff) {
    int c = byteoff >> 4;
    int sc = c ^ (r & 7);
    return (uint32_t)(r * 128 + sc * 16 + (byteoff & 15));
}

__global__ void __launch_bounds__(128) flash_mma(
    const __nv_bfloat16* __restrict__ Qh, const __nv_bfloat16* __restrict__ Ql,
    const __nv_bfloat16* __restrict__ Kh, const __nv_bfloat16* __restrict__ Kl,
    const __nv_bfloat16* __restrict__ Vh, const __nv_bfloat16* __restrict__ Vl,
    __nv_bfloat16* __restrict__ Ch, __nv_bfloat16* __restrict__ Cl)
{
    extern __shared__ char smb[];
    const uint32_t sb = smem_u32(smb);
    const int t = threadIdx.x;
    const int lane = t & 31, w = t >> 5;
    const int g = lane >> 2, t4 = lane & 3;
    const int qi = blockIdx.x, bh = blockIdx.y;
    const size_t hb = (size_t)bh * SS * DH;

    // ldmatrix per-lane precomputed rows
    const int q8 = lane >> 3, rr = lane & 7;
    const int chqA = q8 >> 1, chqB = q8 & 1;
    const int rowQ = w * 16 + rr + ((q8 & 1) << 3);
    const int rowQ256 = rowQ << 8, mQ = rowQ & 7;
    int rK256[4], mK[4], rV128[8], mV[8];
#pragma unroll
    for (int p = 0; p < 4; p++) {
        int r = p * 16 + rr + ((q8 >> 1) << 3);
        rK256[p] = r << 8; mK[p] = r & 7;
    }
#pragma unroll
    for (int p = 0; p < 8; p++) {
        int r = p * 16 + rr + ((q8 >> 1) << 3);
        rV128[p] = r << 7; mV[p] = r & 7;
    }

    // Q tile (hi+lo)
    {
        const __nv_bfloat16* qbh = Qh + hb + (size_t)qi * 64 * DH;
        const __nv_bfloat16* qbl = Ql + hb + (size_t)qi * 64 * DH;
#pragma unroll
        for (int i = 0; i < 8; i++) {
            int id = t + i * 128;
            int r = id >> 4, c = id & 15;
            uint32_t sw = sw256(r, c * 16);
            CP_ASYNC16(sb + FQH + sw, qbh + (size_t)r * DH + c * 8);
            CP_ASYNC16(sb + FQL + sw, qbl + (size_t)r * DH + c * 8);
        }
    }
    CP_COMMIT();

    float o[16][4];
#pragma unroll
    for (int i = 0; i < 16; i++)
#pragma unroll
        for (int j = 0; j < 4; j++) o[i][j] = 0.f;
    float m0 = -1e30f, m1 = -1e30f, l0 = 0.f, l1 = 0.f;

    const int qr0 = w * 16 + g;
    const float scale = 0.08838834764831845f;

    for (int kj = 0; kj <= qi; kj++) {
        __syncthreads();
        {
            const __nv_bfloat16* kbh = Kh + hb + (size_t)kj * 64 * DH;
            const __nv_bfloat16* kbl = Kl + hb + (size_t)kj * 64 * DH;
#pragma unroll
            for (int i = 0; i < 8; i++) {
                int id = t + i * 128;
                int r = id >> 4, c = id & 15;
                uint32_t sw = sw256(r, c * 16);
                CP_ASYNC16(sb + FKH + sw, kbh + (size_t)r * DH + c * 8);
                CP_ASYNC16(sb + FKL + sw, kbl + (size_t)r * DH + c * 8);
            }
            const __nv_bfloat16* vbh = Vh + hb + (size_t)kj * 64;
            const __nv_bfloat16* vbl = Vl + hb + (size_t)kj * 64;
#pragma unroll
            for (int i = 0; i < 8; i++) {
                int id = t + i * 128;
                int r = id >> 3, c = id & 7;
                uint32_t sw = sw128(r, c * 16);
                CP_ASYNC16(sb + FVH + sw, vbh + (size_t)r * SS + c * 8);
                CP_ASYNC16(sb + FVL + sw, vbl + (size_t)r * SS + c * 8);
            }
        }
        CP_COMMIT(); CP_WAIT0();
        __syncthreads();

        // ---- S = Q K^T ----
        float s[8][4];
#pragma unroll
        for (int nt = 0; nt < 8; nt++)
#pragma unroll
            for (int j = 0; j < 4; j++) s[nt][j] = 0.f;

#pragma unroll
        for (int kt = 0; kt < 8; kt++) {
            uint32_t aqh[4], aql[4];
            ldsmx4(aqh, sb + FQH + rowQ256 + ((kt*2 + chqA) ^ mQ) * 16);
            ldsmx4(aql, sb + FQL + rowQ256 + ((kt*2 + chqA) ^ mQ) * 16);
#pragma unroll
            for (int p = 0; p < 4; p++) {
                uint32_t kbh4[4], kbl4[4];
                ldsmx4(kbh4, sb + FKH + rK256[p] + ((kt*2 + chqB) ^ mK[p]) * 16);
                ldsmx4(kbl4, sb + FKL + rK256[p] + ((kt*2 + chqB) ^ mK[p]) * 16);
                mma_bf16(s[2*p],   aqh, kbh4[0], kbh4[1]);
                mma_bf16(s[2*p],   aqh, kbl4[0], kbl4[1]);
                mma_bf16(s[2*p],   aql, kbh4[0], kbh4[1]);
                mma_bf16(s[2*p+1], aqh, kbh4[2], kbh4[3]);
                mma_bf16(s[2*p+1], aqh, kbl4[2], kbl4[3]);
                mma_bf16(s[2*p+1], aql, kbh4[2], kbh4[3]);
            }
        }

#pragma unroll
        for (int nt = 0; nt < 8; nt++)
#pragma unroll
            for (int j = 0; j < 4; j++) s[nt][j] *= scale;
        if (kj == qi) {
#pragma unroll
            for (int nt = 0; nt < 8; nt++) {
                int c0 = nt * 8 + 2 * t4;
                if (c0     > qr0)     s[nt][0] = -1e30f;
                if (c0 + 1 > qr0)     s[nt][1] = -1e30f;
                if (c0     > qr0 + 8) s[nt][2] = -1e30f;
                if (c0 + 1 > qr0 + 8) s[nt][3] = -1e30f;
            }
        }

        // ---- online softmax ----
        float rm0 = -1e30f, rm1 = -1e30f;
#pragma unroll
        for (int nt = 0; nt < 8; nt++) {
            rm0 = fmaxf(rm0, fmaxf(s[nt][0], s[nt][1]));
            rm1 = fmaxf(rm1, fmaxf(s[nt][2], s[nt][3]));
        }
        rm0 = fmaxf(rm0, __shfl_xor_sync(0xffffffff, rm0, 1));
        rm0 = fmaxf(rm0, __shfl_xor_sync(0xffffffff, rm0, 2));
        rm1 = fmaxf(rm1, __shfl_xor_sync(0xffffffff, rm1, 1));
        rm1 = fmaxf(rm1, __shfl_xor_sync(0xffffffff, rm1, 2));
        float mn0 = fmaxf(m0, rm0), mn1 = fmaxf(m1, rm1);
        float al0 = __expf(m0 - mn0), al1 = __expf(m1 - mn1);
        float ls0 = 0.f, ls1 = 0.f;
#pragma unroll
        for (int nt = 0; nt < 8; nt++) {
            s[nt][0] = __expf(s[nt][0] - mn0);
            s[nt][1] = __expf(s[nt][1] - mn0);
            s[nt][2] = __expf(s[nt][2] - mn1);
            s[nt][3] = __expf(s[nt][3] - mn1);
            ls0 += s[nt][0] + s[nt][1];
            ls1 += s[nt][2] + s[nt][3];
        }
        ls0 += __shfl_xor_sync(0xffffffff, ls0, 1);
        ls0 += __shfl_xor_sync(0xffffffff, ls0, 2);
        ls1 += __shfl_xor_sync(0xffffffff, ls1, 1);
        ls1 += __shfl_xor_sync(0xffffffff, ls1, 2);
        l0 = l0 * al0 + ls0;  m0 = mn0;
        l1 = l1 * al1 + ls1;  m1 = mn1;
#pragma unroll
        for (int ntc = 0; ntc < 16; ntc++) {
            o[ntc][0] *= al0; o[ntc][1] *= al0;
            o[ntc][2] *= al1; o[ntc][3] *= al1;
        }

        // ---- PV ----
#pragma unroll
        for (int kt = 0; kt < 4; kt++) {
            uint32_t aph[4], apl[4];
            split2(s[2*kt][0],   s[2*kt][1],   aph[0], apl[0]);
            split2(s[2*kt][2],   s[2*kt][3],   aph[1], apl[1]);
            split2(s[2*kt+1][0], s[2*kt+1][1], aph[2], apl[2]);
            split2(s[2*kt+1][2], s[2*kt+1][3], aph[3], apl[3]);
#pragma unroll
            for (int p = 0; p < 8; p++) {
                uint32_t vh4[4], vl4[4];
                ldsmx4(vh4, sb + FVH + rV128[p] + ((kt*2 + chqB) ^ mV[p]) * 16);
                ldsmx4(vl4, sb + FVL + rV128[p] + ((kt*2 + chqB) ^ mV[p]) * 16);
                mma_bf16(o[2*p],   aph, vh4[0], vh4[1]);
                mma_bf16(o[2*p],   aph, vl4[0], vl4[1]);
                mma_bf16(o[2*p],   apl, vh4[0], vh4[1]);
                mma_bf16(o[2*p+1], aph, vh4[2], vh4[3]);
                mma_bf16(o[2*p+1], aph, vl4[2], vl4[3]);
                mma_bf16(o[2*p+1], apl, vh4[2], vh4[3]);
            }
        }
    }

    // ---- epilogue ----
    const float inv0 = 1.f / l0, inv1 = 1.f / l1;
    const int b = bh >> 4, h = bh & 15;
    const int row0 = qi * 64 + qr0;
#pragma unroll
    for (int ntc = 0; ntc < 16; ntc++) {
        const int col = h * 128 + ntc * 8 + 2 * t4;
        size_t i0 = ((size_t)(b * SS + row0)) * NPROJ + col;
        size_t i1 = ((size_t)(b * SS + row0 + 8)) * NPROJ + col;
        uint32_t h2, l2;
        split2(o[ntc][0] * inv0, o[ntc][1] * inv0, h2, l2);
        *(uint32_t*)(Ch + i0) = h2;
        *(uint32_t*)(Cl + i0) = l2;
        split2(o[ntc][2] * inv1, o[ntc][3] * inv1, h2, l2);
        *(uint32_t*)(Ch + i1) = h2;
        *(uint32_t*)(Cl + i1) = l2;
    }
}

// ---------------- launch ----------------
extern "C" void kernel_launch(void* const* d_in, const int* in_sizes, int n_in,
                              void* d_out, int out_size)
{
    const float* x  = (const float*)d_in[0];
    const float* Wq = (const float*)d_in[1];
    const float* bq = (const float*)d_in[2];
    const float* Wk = (const float*)d_in[3];
    const float* bk = (const float*)d_in[4];
    const float* Wv = (const float*)d_in[5];
    const float* bv = (const float*)d_in[6];
    const float* Wo = (const float*)d_in[7];
    const float* bo = (const float*)d_in[8];
    float* out = (float*)d_out;

    __nv_bfloat16 *xh, *xl, *ch, *cl, *qh, *ql, *kh, *kl, *vh, *vl;
    cudaGetSymbolAddress((void**)&xh, g_xh);
    cudaGetSymbolAddress((void**)&xl, g_xl);
    cudaGetSymbolAddress((void**)&ch, g_ch);
    cudaGetSymbolAddress((void**)&cl, g_cl);
    cudaGetSymbolAddress((void**)&qh, g_qh);
    cudaGetSymbolAddress((void**)&ql, g_ql);
    cudaGetSymbolAddress((void**)&kh, g_kh);
    cudaGetSymbolAddress((void**)&kl, g_kl);
    cudaGetSymbolAddress((void**)&vh, g_vh);
    cudaGetSymbolAddress((void**)&vl, g_vl);
    __nv_bfloat16 *wqh, *wql, *wkh, *wkl, *wvh, *wvl, *woh, *wol;
    cudaGetSymbolAddress((void**)&wqh, g_wqh);
    cudaGetSymbolAddress((void**)&wql, g_wql);
    cudaGetSymbolAddress((void**)&wkh, g_wkh);
    cudaGetSymbolAddress((void**)&wkl, g_wkl);
    cudaGetSymbolAddress((void**)&wvh, g_wvh);
    cudaGetSymbolAddress((void**)&wvl, g_wvl);
    cudaGetSymbolAddress((void**)&woh, g_woh);
    cudaGetSymbolAddress((void**)&wol, g_wol);

    cudaFuncSetAttribute(gemm_qkv, cudaFuncAttributeMaxDynamicSharedMemorySize, GEMM_SMEM);
    cudaFuncSetAttribute(gemm_out, cudaFuncAttributeMaxDynamicSharedMemorySize, GEMM_SMEM);
    cudaFuncSetAttribute(flash_mma, cudaFuncAttributeMaxDynamicSharedMemorySize, FA_SMEM);

    const int n4x = (MTOT * D_MODEL) / 4;
    cvt_hilo<<<(n4x + 255) / 256, 256>>>(x, xh, xl, n4x);
    dim3 tgrid(D_MODEL / 32, D_MODEL / 32, 4);
    transcvt4<<<tgrid, 256>>>(Wq, Wk, Wv, Wo,
                              wqh, wql, wkh, wkl, wvh, wvl, woh, wol);

    dim3 qkvgrid(NPROJ / 128, MTOT / 128, 3);   // (16, 32, 3)
    gemm_qkv<<<qkvgrid, 256, GEMM_SMEM>>>(xh, xl, wqh, wql, wkh, wkl, wvh, wvl,
                                          bq, bk, bv, qh, ql, kh, kl, vh, vl);

    dim3 fgrid(SS / 64, BB * NH);               // (32, 32)
    flash_mma<<<fgrid, 128, FA_SMEM>>>(qh, ql, kh, kl, vh, vl, ch, cl);

    dim3 ogrid(NPROJ / 128, MTOT / 128);        // (16, 32)
    gemm_out<<<ogrid, 256, GEMM_SMEM>>>(ch, cl, woh, wol, bo, out);
}